// round 2
// baseline (speedup 1.0000x reference)
#include <cuda_runtime.h>
#include <cstdint>

// PairManifoldConstrainedHyperConnections — round 2
// x: [65536, 512] fp32.  Per pixel: RMSNorm -> 24 dots -> tanh ->
// sigmoid/sigmoid/sinkhorn(20) -> out [65536, 24] fp32.
//
// Round-2 design: 1 px/thread, 256 thr/CTA (256 px/CTA), 256 CTAs,
// __launch_bounds__(256,2) -> 2 CTAs/SM (16 warps). Warp-private cp.async
// staging (3-deep, 16 floats/px/chunk) -> no __syncthreads in mainloop.
// Weights (24x512) staged once in SMEM quad-major, warp-uniform broadcast LDS.
// Dots on RAW x with fma.rn.f32x2; RMS scale applied to the 24 scalars.

#define TPB 256
#define PXB 256            // pixels per block
#define NWARP 8
#define CQ 4               // float4 per px per chunk (16 floats)
#define NCHUNK 32          // 32 * 16 = 512
#define PITCH 5            // float4 pitch (conflict-free)
#define NBUF 3
#define NW 24

typedef unsigned long long ull;

__device__ __forceinline__ ull fma2(ull a, ull b, ull c) {
    ull d;
    asm("fma.rn.f32x2 %0, %1, %2, %3;" : "=l"(d) : "l"(a), "l"(b), "l"(c));
    return d;
}
__device__ __forceinline__ float lo2(ull v) { return __uint_as_float((unsigned)(v & 0xffffffffull)); }
__device__ __forceinline__ float hi2(ull v) { return __uint_as_float((unsigned)(v >> 32)); }
__device__ __forceinline__ float tanh_a(float x) { float y; asm("tanh.approx.f32 %0, %1;" : "=f"(y) : "f"(x)); return y; }
__device__ __forceinline__ float rcp_a(float x)  { float y; asm("rcp.approx.f32 %0, %1;"  : "=f"(y) : "f"(x)); return y; }
__device__ __forceinline__ float ex2_a(float x)  { float y; asm("ex2.approx.f32 %0, %1;"  : "=f"(y) : "f"(x)); return y; }
__device__ __forceinline__ float exp_a(float x)  { return ex2_a(x * 1.4426950408889634f); }

__device__ __forceinline__ void cp16(uint32_t dst_smem, const void* src) {
    asm volatile("cp.async.ca.shared.global [%0], [%1], 16;" :: "r"(dst_smem), "l"(src) : "memory");
}

__global__ void __launch_bounds__(TPB, 2)
pmchc_kernel(const float4* __restrict__ x4,
             const float4* __restrict__ wpre,
             const float4* __restrict__ wpost,
             const float4* __restrict__ wres,
             const float* __restrict__ bpre,
             const float* __restrict__ bpost,
             const float* __restrict__ bres,
             const float* __restrict__ apre,
             const float* __restrict__ apost,
             const float* __restrict__ ares,
             float* __restrict__ out)
{
    extern __shared__ float4 smem[];
    float4* wsm  = smem;              // [128 quads][24 j]  -> 48 KB
    float4* xbuf = smem + 128 * NW;   // [NBUF][NWARP][32 px][PITCH] -> 60 KB

    const int t = threadIdx.x;
    const int w = t >> 5;
    const int lane = t & 31;
    const int pxbase = blockIdx.x * PXB;
    const uint32_t sbase = (uint32_t)__cvta_generic_to_shared(xbuf);

    // gmem base for this warp's 32 pixels
    const float4* gw = x4 + (size_t)(pxbase + w * 32) * 128;

    // ---- stage chunks 0..1 (warp-private) ----
#pragma unroll
    for (int c = 0; c < 2; c++) {
        uint32_t d = sbase + (uint32_t)((c * NWARP + w) * 32 * PITCH) * 16;
        const float4* g = gw + c * CQ;
#pragma unroll
        for (int it = 0; it < CQ; it++) {
            int i = lane + 32 * it;
            int p = i >> 2, q = i & 3;
            cp16(d + (uint32_t)(p * PITCH + q) * 16, g + (size_t)p * 128 + q);
        }
        asm volatile("cp.async.commit_group;" ::: "memory");
    }

    // ---- stage weights: wsm[q*24 + j]; rows 0-3 pre, 4-7 post, 8-23 res ----
    for (int i = t; i < NW * 128; i += TPB) {
        int q = i / NW, j = i % NW;
        float4 v;
        if (j < 4)       v = wpre[j * 128 + q];
        else if (j < 8)  v = wpost[(j - 4) * 128 + q];
        else             v = wres[(j - 8) * 128 + q];
        wsm[q * NW + j] = v;
    }
    __syncthreads();   // weights visible; x chunks are warp-private

    ull acc[24], ss = 0ull;
#pragma unroll
    for (int j = 0; j < 24; j++) acc[j] = 0ull;

    const int myrow = (w * 32 + lane);  // unused; px = pxbase + w*32 + lane

#pragma unroll 1
    for (int c = 0; c < NCHUNK; c++) {
        // prefetch chunk c+2
        if (c + 2 < NCHUNK) {
            int cn = c + 2;
            uint32_t d = sbase + (uint32_t)(((cn % NBUF) * NWARP + w) * 32 * PITCH) * 16;
            const float4* g = gw + cn * CQ;
#pragma unroll
            for (int it = 0; it < CQ; it++) {
                int i = lane + 32 * it;
                int p = i >> 2, q = i & 3;
                cp16(d + (uint32_t)(p * PITCH + q) * 16, g + (size_t)p * 128 + q);
            }
            asm volatile("cp.async.commit_group;" ::: "memory");
            asm volatile("cp.async.wait_group 2;" ::: "memory");
        } else if (c + 2 == NCHUNK) {
            asm volatile("cp.async.wait_group 1;" ::: "memory");
        } else {
            asm volatile("cp.async.wait_group 0;" ::: "memory");
        }
        __syncwarp();

        const ulonglong2* xb = (const ulonglong2*)
            (xbuf + ((c % NBUF) * NWARP + w) * 32 * PITCH + lane * PITCH);
#pragma unroll
        for (int q = 0; q < CQ; q++) {
            ulonglong2 a = *(const ulonglong2*)((const float4*)xb + q);
            ss = fma2(a.x, a.x, ss);
            ss = fma2(a.y, a.y, ss);
            const ulonglong2* wr = (const ulonglong2*)(wsm + (c * CQ + q) * NW);
#pragma unroll
            for (int j = 0; j < 24; j++) {
                ulonglong2 wv = wr[j];   // warp-uniform broadcast
                acc[j] = fma2(a.x, wv.x, fma2(a.y, wv.y, acc[j]));
            }
        }
    }

    // ---- epilogue (1 px/thread) ----
    const float a_pre = __ldg(apre), a_post = __ldg(apost), a_res = __ldg(ares);

    float ssv = lo2(ss) + hi2(ss);
    float s = rsqrtf(ssv * (1.0f / 512.0f) + 1.1920929e-07f);

    float d[24];
#pragma unroll
    for (int j = 0; j < 24; j++) d[j] = (lo2(acc[j]) + hi2(acc[j])) * s;

    float4 o0, o1;
    float* po0 = (float*)&o0;
    float* po1 = (float*)&o1;
#pragma unroll
    for (int j = 0; j < 4; j++) {
        po0[j] =        rcp_a(1.0f + exp_a(-(a_pre  * tanh_a(d[j])     + __ldg(bpre + j))));
        po1[j] = 2.0f * rcp_a(1.0f + exp_a(-(a_post * tanh_a(d[4 + j]) + __ldg(bpost + j))));
    }

    float M[16];
#pragma unroll
    for (int k = 0; k < 16; k++) M[k] = exp_a(a_res * tanh_a(d[8 + k]) + __ldg(bres + k));

#pragma unroll 1
    for (int it = 0; it < 20; it++) {
#pragma unroll
        for (int i = 0; i < 4; i++) {
            float r = rcp_a(M[i*4] + M[i*4+1] + M[i*4+2] + M[i*4+3]);
            M[i*4] *= r; M[i*4+1] *= r; M[i*4+2] *= r; M[i*4+3] *= r;
        }
#pragma unroll
        for (int j = 0; j < 4; j++) {
            float r = rcp_a(M[j] + M[4+j] + M[8+j] + M[12+j]);
            M[j] *= r; M[4+j] *= r; M[8+j] *= r; M[12+j] *= r;
        }
    }

    float4* o4 = (float4*)(out + (size_t)(pxbase + w * 32 + lane) * 24);
    o4[0] = o0;
    o4[1] = o1;
#pragma unroll
    for (int i = 0; i < 4; i++)
        o4[2 + i] = make_float4(M[i*4], M[i*4+1], M[i*4+2], M[i*4+3]);
}

extern "C" void kernel_launch(void* const* d_in, const int* in_sizes, int n_in,
                              void* d_out, int out_size)
{
    const float4* x4    = (const float4*)d_in[0];
    const float4* wpre  = (const float4*)d_in[1];
    const float4* wpost = (const float4*)d_in[2];
    const float4* wres  = (const float4*)d_in[3];
    const float*  bpre  = (const float*)d_in[4];
    const float*  bpost = (const float*)d_in[5];
    const float*  bres  = (const float*)d_in[6];
    const float*  apre  = (const float*)d_in[7];
    const float*  apost = (const float*)d_in[8];
    const float*  ares  = (const float*)d_in[9];
    float* out = (float*)d_out;

    int px = in_sizes[0] / 512;     // 65536
    int blocks = px / PXB;          // 256

    size_t smem = (size_t)(128 * NW + NBUF * NWARP * 32 * PITCH) * sizeof(float4); // 110592 B
    cudaFuncSetAttribute(pmchc_kernel, cudaFuncAttributeMaxDynamicSharedMemorySize, (int)smem);

    pmchc_kernel<<<blocks, TPB, smem>>>(x4, wpre, wpost, wres,
                                        bpre, bpost, bres,
                                        apre, apost, ares, out);
}

// round 4
// speedup vs baseline: 1.7595x; 1.7595x over previous
#include <cuda_runtime.h>
#include <cstdint>

// PairManifoldConstrainedHyperConnections — round 4: warp-level HMMA (mma.sync bf16).
// D[65536,24] = x[65536,512] @ W^T via m16n8k16 bf16 mma.sync (sm_80+ PTX, works at
// compute_100). Warp owns 64 px (4 m16 tiles x 3 n8 tiles). cp.async double-buffered
// 32-float k-chunks, fully warp-private mainloop (no __syncthreads after init).
// RMS sum-of-squares kept in fp32 from the same loads. Epilogue: sinkhorn(20).

#define TPB 128
#define XPITCH 40                        // floats per px row in smem (32 + 8 pad)
#define XBUF_BYTES (2 * 256 * XPITCH * 4)        // 81920
#define SM_WFRAG   XBUF_BYTES                    // 3072 ull = 24576 B
#define SM_SS      (SM_WFRAG + 24576)            // 256 floats
#define SM_TOTAL   (SM_SS + 1024)                // 107520 B

typedef unsigned long long ull;

__device__ __forceinline__ uint32_t bf16x2(float lo, float hi){
    uint32_t r; asm("cvt.rn.bf16x2.f32 %0, %1, %2;" : "=r"(r) : "f"(hi), "f"(lo)); return r;
}
__device__ __forceinline__ float tanh_a(float x){ float y; asm("tanh.approx.f32 %0, %1;" : "=f"(y) : "f"(x)); return y; }
__device__ __forceinline__ float rcp_a(float x){ float y; asm("rcp.approx.f32 %0, %1;" : "=f"(y) : "f"(x)); return y; }
__device__ __forceinline__ float ex2_a(float x){ float y; asm("ex2.approx.f32 %0, %1;" : "=f"(y) : "f"(x)); return y; }
__device__ __forceinline__ float exp_a(float x){ return ex2_a(x * 1.4426950408889634f); }

__device__ __forceinline__ void cp16(uint32_t dst, const void* src){
    asm volatile("cp.async.ca.shared.global [%0], [%1], 16;" :: "r"(dst), "l"(src) : "memory");
}
#define CP_COMMIT() asm volatile("cp.async.commit_group;" ::: "memory")
#define CP_WAIT(n)  asm volatile("cp.async.wait_group %0;" :: "n"(n) : "memory")

__device__ __forceinline__ void mma_bf16(float* d, uint32_t a0, uint32_t a1,
                                         uint32_t a2, uint32_t a3,
                                         uint32_t b0, uint32_t b1){
    asm volatile(
        "mma.sync.aligned.m16n8k16.row.col.f32.bf16.bf16.f32 "
        "{%0,%1,%2,%3}, {%4,%5,%6,%7}, {%8,%9}, {%0,%1,%2,%3};"
        : "+f"(d[0]), "+f"(d[1]), "+f"(d[2]), "+f"(d[3])
        : "r"(a0), "r"(a1), "r"(a2), "r"(a3), "r"(b0), "r"(b1));
}

__device__ __forceinline__ void epilogue_px(
    const float* dv, float ssv,
    float a_pre, float a_post, float a_res,
    const float* __restrict__ bpre, const float* __restrict__ bpost,
    const float* __restrict__ bres, float* __restrict__ o)
{
    float sc = rsqrtf(ssv * (1.0f / 512.0f) + 1.1920929e-07f);
    float d[24];
#pragma unroll
    for (int j = 0; j < 24; j++) d[j] = dv[j] * sc;

    float4 o0, o1;
    float* po0 = (float*)&o0;
    float* po1 = (float*)&o1;
#pragma unroll
    for (int j = 0; j < 4; j++) {
        po0[j] =        rcp_a(1.0f + exp_a(-(a_pre  * tanh_a(d[j])     + __ldg(bpre + j))));
        po1[j] = 2.0f * rcp_a(1.0f + exp_a(-(a_post * tanh_a(d[4 + j]) + __ldg(bpost + j))));
    }

    float M[16];
#pragma unroll
    for (int k = 0; k < 16; k++) M[k] = exp_a(a_res * tanh_a(d[8 + k]) + __ldg(bres + k));

#pragma unroll 1
    for (int it = 0; it < 20; it++) {
#pragma unroll
        for (int i = 0; i < 4; i++) {
            float r = rcp_a(M[i*4] + M[i*4+1] + M[i*4+2] + M[i*4+3]);
            M[i*4] *= r; M[i*4+1] *= r; M[i*4+2] *= r; M[i*4+3] *= r;
        }
#pragma unroll
        for (int j = 0; j < 4; j++) {
            float r = rcp_a(M[j] + M[4+j] + M[8+j] + M[12+j]);
            M[j] *= r; M[4+j] *= r; M[8+j] *= r; M[12+j] *= r;
        }
    }

    float4* o4 = (float4*)o;
    o4[0] = o0;
    o4[1] = o1;
#pragma unroll
    for (int i = 0; i < 4; i++)
        o4[2 + i] = make_float4(M[i*4], M[i*4+1], M[i*4+2], M[i*4+3]);
}

__global__ void __launch_bounds__(TPB, 2)
pmchc_hmma(const float* __restrict__ x,
           const float* __restrict__ wpre,
           const float* __restrict__ wpost,
           const float* __restrict__ wres,
           const float* __restrict__ bpre,
           const float* __restrict__ bpost,
           const float* __restrict__ bres,
           const float* __restrict__ apre,
           const float* __restrict__ apost,
           const float* __restrict__ ares,
           float* __restrict__ out)
{
    extern __shared__ char smem[];
    float* xbuf  = (float*)smem;                       // [2][256][XPITCH]
    ull*   wfrag = (ull*)(smem + SM_WFRAG);            // [32 kstep][3 ntile][32 lane]
    float* sssm  = (float*)(smem + SM_SS);             // [256]
    const uint32_t sb = (uint32_t)__cvta_generic_to_shared(smem);

    const int t = threadIdx.x, w = t >> 5, l = t & 31;
    const int gr = l >> 2, c2 = (l & 3) * 2;
    const int pxbase = blockIdx.x * 256;

    const float* gx = x + (size_t)(pxbase + w * 64) * 512;

    // ---- kick off chunk-0 staging (warp-private: warp w stages its 64 rows) ----
    {
        uint32_t db = sb + (uint32_t)(w * 64 * XPITCH) * 4;
#pragma unroll
        for (int it = 0; it < 16; it++) {
            int lin = l + 32 * it, r = lin >> 3, seg = lin & 7;
            cp16(db + (uint32_t)(r * XPITCH + seg * 4) * 4, gx + (size_t)r * 512 + seg * 4);
        }
        CP_COMMIT();
    }

    // ---- build fragment-ready bf16 weights: entry i = (kstep*3 + ntile)*32 + lane ----
    for (int i = t; i < 3072; i += TPB) {
        int lane = i & 31, nt = (i >> 5) % 3, s = i / 96;
        int j = nt * 8 + (lane >> 2);
        int k0 = s * 16 + (lane & 3) * 2;
        const float* wr = (j < 4) ? wpre + j * 512
                        : (j < 8) ? wpost + (j - 4) * 512
                                  : wres + (j - 8) * 512;
        float2 p0 = *(const float2*)(wr + k0);
        float2 p1 = *(const float2*)(wr + k0 + 8);
        wfrag[i] = (ull)bf16x2(p0.x, p0.y) | ((ull)bf16x2(p1.x, p1.y) << 32);
    }
    __syncthreads();   // wfrag visible to all warps (only block barrier)

    float acc[4][12];
    float ssv[4][2];
#pragma unroll
    for (int i = 0; i < 4; i++) {
        ssv[i][0] = ssv[i][1] = 0.f;
#pragma unroll
        for (int j = 0; j < 12; j++) acc[i][j] = 0.f;
    }

#pragma unroll 1
    for (int ch = 0; ch < 16; ch++) {
        if (ch < 15) {
            uint32_t db = sb + (uint32_t)((((ch + 1) & 1) * 256 + w * 64) * XPITCH) * 4;
            const float* g = gx + (ch + 1) * 32;
#pragma unroll
            for (int it = 0; it < 16; it++) {
                int lin = l + 32 * it, r = lin >> 3, seg = lin & 7;
                cp16(db + (uint32_t)(r * XPITCH + seg * 4) * 4, g + (size_t)r * 512 + seg * 4);
            }
            CP_COMMIT();
            CP_WAIT(1);
        } else {
            CP_WAIT(0);
        }
        __syncwarp();

        const float* xb = xbuf + ((ch & 1) * 256 + w * 64) * XPITCH;
#pragma unroll
        for (int kk = 0; kk < 2; kk++) {
            int ks = ch * 2 + kk;
            ull B0 = wfrag[(ks * 3 + 0) * 32 + l];
            ull B1 = wfrag[(ks * 3 + 1) * 32 + l];
            ull B2 = wfrag[(ks * 3 + 2) * 32 + l];
#pragma unroll
            for (int tile = 0; tile < 4; tile++) {
                const float* xr = xb + (tile * 16 + gr) * XPITCH + kk * 16 + c2;
                float2 v0 = *(const float2*)(xr);
                float2 v1 = *(const float2*)(xr + 8 * XPITCH);
                float2 v2 = *(const float2*)(xr + 8);
                float2 v3 = *(const float2*)(xr + 8 * XPITCH + 8);
                ssv[tile][0] += v0.x*v0.x + v0.y*v0.y + v2.x*v2.x + v2.y*v2.y;
                ssv[tile][1] += v1.x*v1.x + v1.y*v1.y + v3.x*v3.x + v3.y*v3.y;
                uint32_t a0 = bf16x2(v0.x, v0.y);
                uint32_t a1 = bf16x2(v1.x, v1.y);
                uint32_t a2 = bf16x2(v2.x, v2.y);
                uint32_t a3 = bf16x2(v3.x, v3.y);
                mma_bf16(acc[tile] + 0, a0, a1, a2, a3, (uint32_t)B0, (uint32_t)(B0 >> 32));
                mma_bf16(acc[tile] + 4, a0, a1, a2, a3, (uint32_t)B1, (uint32_t)(B1 >> 32));
                mma_bf16(acc[tile] + 8, a0, a1, a2, a3, (uint32_t)B2, (uint32_t)(B2 >> 32));
            }
        }
    }

    // ---- ss: reduce over the 4 lanes of each quad (they cover disjoint k) ----
#pragma unroll
    for (int tile = 0; tile < 4; tile++) {
#pragma unroll
        for (int h = 0; h < 2; h++) {
            float s = ssv[tile][h];
            s += __shfl_xor_sync(0xffffffffu, s, 1);
            s += __shfl_xor_sync(0xffffffffu, s, 2);
            if ((l & 3) == 0)
                sssm[w * 64 + tile * 16 + h * 8 + gr] = s;
        }
    }

    // ---- stage D into (dead) x-buffer 0, warp-private rows ----
    float* dw = xbuf + w * 64 * XPITCH;
#pragma unroll
    for (int tile = 0; tile < 4; tile++) {
#pragma unroll
        for (int nt = 0; nt < 3; nt++) {
            int col = nt * 8 + c2;
            *(float2*)(dw + (tile * 16 + gr)     * XPITCH + col) = make_float2(acc[tile][nt*4+0], acc[tile][nt*4+1]);
            *(float2*)(dw + (tile * 16 + gr + 8) * XPITCH + col) = make_float2(acc[tile][nt*4+2], acc[tile][nt*4+3]);
        }
    }
    __syncwarp();

    // ---- epilogue: 2 px per lane ----
    const float a_pre = __ldg(apre), a_post = __ldg(apost), a_res = __ldg(ares);
#pragma unroll
    for (int h = 0; h < 2; h++) {
        int pl = l + h * 32;                       // local px within warp (0..63)
        float dv[24];
        const float4* dr = (const float4*)(dw + pl * XPITCH);
#pragma unroll
        for (int q = 0; q < 6; q++) ((float4*)dv)[q] = dr[q];
        epilogue_px(dv, sssm[w * 64 + pl], a_pre, a_post, a_res,
                    bpre, bpost, bres,
                    out + (size_t)(pxbase + w * 64 + pl) * 24);
    }
}

extern "C" void kernel_launch(void* const* d_in, const int* in_sizes, int n_in,
                              void* d_out, int out_size)
{
    const float* x     = (const float*)d_in[0];
    const float* wpre  = (const float*)d_in[1];
    const float* wpost = (const float*)d_in[2];
    const float* wres  = (const float*)d_in[3];
    const float* bpre  = (const float*)d_in[4];
    const float* bpost = (const float*)d_in[5];
    const float* bres  = (const float*)d_in[6];
    const float* apre  = (const float*)d_in[7];
    const float* apost = (const float*)d_in[8];
    const float* ares  = (const float*)d_in[9];
    float* out = (float*)d_out;

    int px = in_sizes[0] / 512;    // 65536
    int blocks = px / 256;         // 256

    cudaFuncSetAttribute(pmchc_hmma, cudaFuncAttributeMaxDynamicSharedMemorySize, SM_TOTAL);
    pmchc_hmma<<<blocks, TPB, SM_TOTAL>>>(x, wpre, wpost, wres,
                                          bpre, bpost, bres,
                                          apre, apost, ares, out);
}

// round 5
// speedup vs baseline: 2.4201x; 1.3754x over previous
#include <cuda_runtime.h>
#include <cstdint>

// PairManifoldConstrainedHyperConnections — round 5.
// HMMA mma.sync bf16, 32 px/warp, 128 thr/CTA, 4 CTAs/SM (16 warps/SM),
// 512 CTAs = one balanced wave. Fragment-ready bf16 weights prebuilt into a
// __device__ global by an init kernel (frees smem; L1-resident __ldg in loop).
// x streamed with cp.async.cg (L2-only) double-buffered 32-float chunks,
// fully warp-private mainloop. RMS ss in fp32. Epilogue sinkhorn(20).

#define TPB 128
#define XPITCH 40                               // floats per px row (32 + 8 pad)
#define XBUF_FLOATS (2 * 128 * XPITCH)          // 10240 floats = 40960 B
#define SM_SS     (XBUF_FLOATS * 4)             // 128 floats
#define SM_TOTAL  (SM_SS + 512)                 // 41472 B

typedef unsigned long long ull;

__device__ ull wfrag_g[3072];                   // [32 kstep][3 ntile][32 lane]

__device__ __forceinline__ uint32_t bf16x2(float lo, float hi){
    uint32_t r; asm("cvt.rn.bf16x2.f32 %0, %1, %2;" : "=r"(r) : "f"(hi), "f"(lo)); return r;
}
__device__ __forceinline__ float tanh_a(float x){ float y; asm("tanh.approx.f32 %0, %1;" : "=f"(y) : "f"(x)); return y; }
__device__ __forceinline__ float rcp_a(float x){ float y; asm("rcp.approx.f32 %0, %1;" : "=f"(y) : "f"(x)); return y; }
__device__ __forceinline__ float ex2_a(float x){ float y; asm("ex2.approx.f32 %0, %1;" : "=f"(y) : "f"(x)); return y; }
__device__ __forceinline__ float exp_a(float x){ return ex2_a(x * 1.4426950408889634f); }

__device__ __forceinline__ void cp16(uint32_t dst, const void* src){
    asm volatile("cp.async.cg.shared.global [%0], [%1], 16;" :: "r"(dst), "l"(src) : "memory");
}
#define CP_COMMIT() asm volatile("cp.async.commit_group;" ::: "memory")
#define CP_WAIT(n)  asm volatile("cp.async.wait_group %0;" :: "n"(n) : "memory")

__device__ __forceinline__ void mma_bf16(float* d, uint32_t a0, uint32_t a1,
                                         uint32_t a2, uint32_t a3,
                                         uint32_t b0, uint32_t b1){
    asm volatile(
        "mma.sync.aligned.m16n8k16.row.col.f32.bf16.bf16.f32 "
        "{%0,%1,%2,%3}, {%4,%5,%6,%7}, {%8,%9}, {%0,%1,%2,%3};"
        : "+f"(d[0]), "+f"(d[1]), "+f"(d[2]), "+f"(d[3])
        : "r"(a0), "r"(a1), "r"(a2), "r"(a3), "r"(b0), "r"(b1));
}

// ---- init: build fragment-ready bf16 weights once per launch ----
__global__ void pmchc_init(const float* __restrict__ wpre,
                           const float* __restrict__ wpost,
                           const float* __restrict__ wres)
{
    int i = blockIdx.x * blockDim.x + threadIdx.x;
    if (i >= 3072) return;
    int lane = i & 31, nt = (i >> 5) % 3, s = i / 96;
    int j = nt * 8 + (lane >> 2);
    int k0 = s * 16 + (lane & 3) * 2;
    const float* wr = (j < 4) ? wpre + j * 512
                    : (j < 8) ? wpost + (j - 4) * 512
                              : wres + (j - 8) * 512;
    float2 p0 = *(const float2*)(wr + k0);
    float2 p1 = *(const float2*)(wr + k0 + 8);
    wfrag_g[i] = (ull)bf16x2(p0.x, p0.y) | ((ull)bf16x2(p1.x, p1.y) << 32);
}

__global__ void __launch_bounds__(TPB, 4)
pmchc_hmma(const float* __restrict__ x,
           const float* __restrict__ bpre,
           const float* __restrict__ bpost,
           const float* __restrict__ bres,
           const float* __restrict__ apre,
           const float* __restrict__ apost,
           const float* __restrict__ ares,
           float* __restrict__ out)
{
    extern __shared__ char smem[];
    float* xbuf = (float*)smem;                 // [2][128 px][XPITCH]
    float* sssm = (float*)(smem + SM_SS);       // [128]
    const uint32_t sb = (uint32_t)__cvta_generic_to_shared(smem);

    const int t = threadIdx.x, w = t >> 5, l = t & 31;
    const int gr = l >> 2, c2 = (l & 3) * 2;
    const int pxbase = blockIdx.x * 128;

    const float* gx = x + (size_t)(pxbase + w * 32) * 512;
    const uint32_t wb = (uint32_t)(w * 32 * XPITCH) * 4;

    // stage chunk 0 (warp-private 32 rows x 32 floats)
#pragma unroll
    for (int it = 0; it < 8; it++) {
        int lin = l + 32 * it, r = lin >> 3, seg = lin & 7;
        cp16(sb + wb + (uint32_t)(r * XPITCH + seg * 4) * 4, gx + (size_t)r * 512 + seg * 4);
    }
    CP_COMMIT();

    float acc[2][12];
    float ssv[2][2];
#pragma unroll
    for (int i = 0; i < 2; i++) {
        ssv[i][0] = ssv[i][1] = 0.f;
#pragma unroll
        for (int j = 0; j < 12; j++) acc[i][j] = 0.f;
    }

#pragma unroll 1
    for (int ch = 0; ch < 16; ch++) {
        if (ch < 15) {
            uint32_t db = sb + (uint32_t)(((ch + 1) & 1) * 128 * XPITCH) * 4 + wb;
            const float* g = gx + (ch + 1) * 32;
#pragma unroll
            for (int it = 0; it < 8; it++) {
                int lin = l + 32 * it, r = lin >> 3, seg = lin & 7;
                cp16(db + (uint32_t)(r * XPITCH + seg * 4) * 4, g + (size_t)r * 512 + seg * 4);
            }
            CP_COMMIT();
            CP_WAIT(1);
        } else {
            CP_WAIT(0);
        }
        __syncwarp();

        const float* xb = xbuf + ((ch & 1) * 128 + w * 32) * XPITCH;
#pragma unroll
        for (int kk = 0; kk < 2; kk++) {
            int ks = ch * 2 + kk;
            ull B0 = __ldg(&wfrag_g[(ks * 3 + 0) * 32 + l]);
            ull B1 = __ldg(&wfrag_g[(ks * 3 + 1) * 32 + l]);
            ull B2 = __ldg(&wfrag_g[(ks * 3 + 2) * 32 + l]);
#pragma unroll
            for (int tile = 0; tile < 2; tile++) {
                const float* xr = xb + (tile * 16 + gr) * XPITCH + kk * 16 + c2;
                float2 v0 = *(const float2*)(xr);
                float2 v1 = *(const float2*)(xr + 8 * XPITCH);
                float2 v2 = *(const float2*)(xr + 8);
                float2 v3 = *(const float2*)(xr + 8 * XPITCH + 8);
                ssv[tile][0] += v0.x*v0.x + v0.y*v0.y + v2.x*v2.x + v2.y*v2.y;
                ssv[tile][1] += v1.x*v1.x + v1.y*v1.y + v3.x*v3.x + v3.y*v3.y;
                uint32_t a0 = bf16x2(v0.x, v0.y);
                uint32_t a1 = bf16x2(v1.x, v1.y);
                uint32_t a2 = bf16x2(v2.x, v2.y);
                uint32_t a3 = bf16x2(v3.x, v3.y);
                mma_bf16(acc[tile] + 0, a0, a1, a2, a3, (uint32_t)B0, (uint32_t)(B0 >> 32));
                mma_bf16(acc[tile] + 4, a0, a1, a2, a3, (uint32_t)B1, (uint32_t)(B1 >> 32));
                mma_bf16(acc[tile] + 8, a0, a1, a2, a3, (uint32_t)B2, (uint32_t)(B2 >> 32));
            }
        }
    }

    // ---- per-pixel ss: reduce over the 4 lanes of each quad ----
#pragma unroll
    for (int tile = 0; tile < 2; tile++) {
#pragma unroll
        for (int h = 0; h < 2; h++) {
            float s = ssv[tile][h];
            s += __shfl_xor_sync(0xffffffffu, s, 1);
            s += __shfl_xor_sync(0xffffffffu, s, 2);
            if ((l & 3) == 0)
                sssm[w * 32 + tile * 16 + h * 8 + gr] = s;
        }
    }

    // ---- stage D into dead buffer 0 (warp-private rows) ----
    float* dw = xbuf + w * 32 * XPITCH;
#pragma unroll
    for (int tile = 0; tile < 2; tile++) {
#pragma unroll
        for (int nt = 0; nt < 3; nt++) {
            int col = nt * 8 + c2;
            *(float2*)(dw + (tile * 16 + gr)     * XPITCH + col) = make_float2(acc[tile][nt*4+0], acc[tile][nt*4+1]);
            *(float2*)(dw + (tile * 16 + gr + 8) * XPITCH + col) = make_float2(acc[tile][nt*4+2], acc[tile][nt*4+3]);
        }
    }
    __syncwarp();

    // ---- epilogue: 1 px per lane ----
    const float a_pre = __ldg(apre), a_post = __ldg(apost), a_res = __ldg(ares);

    float dv[24];
    const float4* drd = (const float4*)(dw + l * XPITCH);
#pragma unroll
    for (int q = 0; q < 6; q++) ((float4*)dv)[q] = drd[q];

    float sc = rsqrtf(sssm[w * 32 + l] * (1.0f / 512.0f) + 1.1920929e-07f);
#pragma unroll
    for (int j = 0; j < 24; j++) dv[j] *= sc;

    float4 o0, o1;
    float* po0 = (float*)&o0;
    float* po1 = (float*)&o1;
#pragma unroll
    for (int j = 0; j < 4; j++) {
        po0[j] =        rcp_a(1.0f + exp_a(-(a_pre  * tanh_a(dv[j])     + __ldg(bpre + j))));
        po1[j] = 2.0f * rcp_a(1.0f + exp_a(-(a_post * tanh_a(dv[4 + j]) + __ldg(bpost + j))));
    }

    float M[16];
#pragma unroll
    for (int k = 0; k < 16; k++) M[k] = exp_a(a_res * tanh_a(dv[8 + k]) + __ldg(bres + k));

#pragma unroll 1
    for (int it = 0; it < 20; it++) {
#pragma unroll
        for (int i = 0; i < 4; i++) {
            float r = rcp_a(M[i*4] + M[i*4+1] + M[i*4+2] + M[i*4+3]);
            M[i*4] *= r; M[i*4+1] *= r; M[i*4+2] *= r; M[i*4+3] *= r;
        }
#pragma unroll
        for (int j = 0; j < 4; j++) {
            float r = rcp_a(M[j] + M[4+j] + M[8+j] + M[12+j]);
            M[j] *= r; M[4+j] *= r; M[8+j] *= r; M[12+j] *= r;
        }
    }

    float4* o4 = (float4*)(out + (size_t)(pxbase + w * 32 + l) * 24);
    o4[0] = o0;
    o4[1] = o1;
#pragma unroll
    for (int i = 0; i < 4; i++)
        o4[2 + i] = make_float4(M[i*4], M[i*4+1], M[i*4+2], M[i*4+3]);
}

extern "C" void kernel_launch(void* const* d_in, const int* in_sizes, int n_in,
                              void* d_out, int out_size)
{
    const float* x     = (const float*)d_in[0];
    const float* wpre  = (const float*)d_in[1];
    const float* wpost = (const float*)d_in[2];
    const float* wres  = (const float*)d_in[3];
    const float* bpre  = (const float*)d_in[4];
    const float* bpost = (const float*)d_in[5];
    const float* bres  = (const float*)d_in[6];
    const float* apre  = (const float*)d_in[7];
    const float* apost = (const float*)d_in[8];
    const float* ares  = (const float*)d_in[9];
    float* out = (float*)d_out;

    int px = in_sizes[0] / 512;    // 65536
    int blocks = px / 128;         // 512

    pmchc_init<<<24, 128>>>(wpre, wpost, wres);

    cudaFuncSetAttribute(pmchc_hmma, cudaFuncAttributeMaxDynamicSharedMemorySize, SM_TOTAL);
    pmchc_hmma<<<blocks, TPB, SM_TOTAL>>>(x, bpre, bpost, bres,
                                          apre, apost, ares, out);
}